// round 9
// baseline (speedup 1.0000x reference)
#include <cuda_runtime.h>

#define NB 16
#define NC 64
#define NH 128
#define NW 128
#define NE 8
#define NGH 16

typedef unsigned long long ull;

__device__ float g_pooled[NB * NC];
__device__ float g_probs[NB][NE];
__device__ float g_wcomb[NB * NC * NC * 9];
__device__ float g_bcomb[NB][NC];

#define PACK2(d, lo, hi) \
    asm("mov.b64 %0, {%1, %2};" : "=l"(d) : "f"(lo), "f"(hi))
#define UNPACK2(lo, hi, d) \
    asm("mov.b64 {%0, %1}, %2;" : "=f"(lo), "=f"(hi) : "l"(d))
#define FMA2(d, a, b) \
    asm("fma.rn.f32x2 %0, %1, %2, %0;" : "+l"(d) : "l"(a), "l"(b))

// ---------------------------------------------------------------------------
// Kernel 1a: parallel GAP. One block per (b, c): 1024 blocks.
// ---------------------------------------------------------------------------
__global__ __launch_bounds__(256)
void pool_kernel(const float* __restrict__ x) {
    const int bc = blockIdx.x;
    const int tid = threadIdx.x;
    const float4* p4 = (const float4*)(x + (size_t)bc * NH * NW);

    float s = 0.f;
    #pragma unroll 4
    for (int i = tid; i < (NH * NW) / 4; i += 256) {
        float4 v = p4[i];
        s += (v.x + v.y) + (v.z + v.w);
    }
    #pragma unroll
    for (int o = 16; o > 0; o >>= 1) s += __shfl_xor_sync(0xffffffffu, s, o);

    __shared__ float ws[8];
    if ((tid & 31) == 0) ws[tid >> 5] = s;
    __syncthreads();
    if (tid == 0) {
        float t = 0.f;
        #pragma unroll
        for (int w = 0; w < 8; w++) t += ws[w];
        g_pooled[bc] = t * (1.0f / (NH * NW));
    }
}

// ---------------------------------------------------------------------------
// Kernel 1b: gating MLP + softmax + top-2. One block per batch (tiny).
// ---------------------------------------------------------------------------
__global__ void gate_kernel(const float* __restrict__ wg1,
                            const float* __restrict__ bg1,
                            const float* __restrict__ wg2,
                            const float* __restrict__ bg2) {
    const int b = blockIdx.x;
    const int tid = threadIdx.x;  // 64 threads

    __shared__ float pooled[NC];
    __shared__ float hbuf[NGH];
    __shared__ float logits[NE];

    if (tid < NC) pooled[tid] = g_pooled[b * NC + tid];
    __syncthreads();

    if (tid < NGH) {
        float a = bg1[tid];
        #pragma unroll
        for (int c = 0; c < NC; c++) a += pooled[c] * wg1[c * NGH + tid];
        hbuf[tid] = a > 0.f ? a : 0.f;
    }
    __syncthreads();

    if (tid < NE) {
        float a = bg2[tid];
        #pragma unroll
        for (int g = 0; g < NGH; g++) a += hbuf[g] * wg2[g * NE + tid];
        logits[tid] = a;
    }
    __syncthreads();

    if (tid == 0) {
        float m = -1e30f;
        #pragma unroll
        for (int e = 0; e < NE; e++) m = fmaxf(m, logits[e]);
        float p[NE], s = 0.f;
        #pragma unroll
        for (int e = 0; e < NE; e++) { p[e] = expf(logits[e] - m); s += p[e]; }
        float inv = 1.0f / s;
        #pragma unroll
        for (int e = 0; e < NE; e++) p[e] *= inv;
        int i1 = 0;
        #pragma unroll
        for (int e = 1; e < NE; e++) if (p[e] > p[i1]) i1 = e;
        int i2 = -1;
        #pragma unroll
        for (int e = 0; e < NE; e++) {
            if (e == i1) continue;
            if (i2 < 0 || p[e] > p[i2]) i2 = e;
        }
        float denom = p[i1] + p[i2] + 1e-8f;
        #pragma unroll
        for (int e = 0; e < NE; e++)
            g_probs[b][e] = (e == i1 || e == i2) ? p[e] / denom : 0.f;
    }
}

// ---------------------------------------------------------------------------
// Kernel 2: fold routing probs into per-batch conv weights + bias.
// ---------------------------------------------------------------------------
__global__ void combine_kernel(const float* __restrict__ w_exp,
                               const float* __restrict__ b_exp) {
    const int idx = blockIdx.x * blockDim.x + threadIdx.x;
    const int total = NB * NC * NC * 9;
    if (idx < total) {
        const int b = idx / (NC * NC * 9);
        const int r = idx - b * (NC * NC * 9);   // co*(NC*9) + ci*9 + tap
        const int co = r / (NC * 9);
        const int r2 = r - co * (NC * 9);        // ci*9 + tap
        float s = 0.f;
        #pragma unroll
        for (int e = 0; e < NE; e++)
            s += g_probs[b][e] * w_exp[((size_t)(e * NC + co) * NC) * 9 + r2];
        g_wcomb[idx] = s;
    }
    if (idx < NB * NC) {
        const int b = idx / NC, c = idx - b * NC;
        float s = 0.f;
        #pragma unroll
        for (int e = 0; e < NE; e++) s += g_probs[b][e] * b_exp[e * NC + c];
        g_bcomb[b][c] = s;
    }
}

// ---------------------------------------------------------------------------
// Kernel 3: per-batch 3x3 SAME conv, fused bias + residual, f32x2 FMA.
// Tile 32(w) x 64(h). Block 256 = 8(px) x 32(py); each thread: 4(dx) x 2(dy)
// outputs for 4 c_out (TCO=4 so acc+rows fit in ~105 regs: no spill, and
// ptxas has slack to hoist weight LDS across co iterations).
// Grid: (8 tiles, 16 cog, 16 b) = 2048 blocks.
// ---------------------------------------------------------------------------
#define TCI 4
#define TCO 4

__global__ __launch_bounds__(256, 2)
void conv_kernel(const float* __restrict__ x, float* __restrict__ out) {
    const int tile = blockIdx.x;          // 0..7: 4 x-tiles, 2 y-tiles
    const int cog  = blockIdx.y;          // 0..15
    const int b    = blockIdx.z;          // 0..15
    const int tx = tile & 3, tyi = tile >> 2;
    const int X0 = tx * 32, Y0 = tyi * 64;

    const int tid = threadIdx.x;
    const int px = tid & 7, py = tid >> 3;   // 8 x 32

    __shared__ float  in_s[TCI][66][36];     // 66 rows (64+2 halo), stride 144B
    __shared__ float2 w2_s[TCO][TCI][9];     // duplicated weights {w,w}

    ull acc2[TCO][2][2];                     // [co][dy][pair] = 16 ull
    #pragma unroll
    for (int co = 0; co < TCO; co++)
        #pragma unroll
        for (int dy = 0; dy < 2; dy++) {
            acc2[co][dy][0] = 0ull;
            acc2[co][dy][1] = 0ull;
        }

    const float* xb = x + (size_t)b * NC * NH * NW;
    const float* wb = g_wcomb + (size_t)b * NC * NC * 9;

    for (int cb = 0; cb < NC / TCI; cb++) {
        __syncthreads();
        // stage input: TCI channels x 66x34 (zero-padded halo)
        for (int i = tid; i < TCI * 66 * 34; i += 256) {
            const int ci = i / (66 * 34);
            const int rr = i - ci * (66 * 34);
            const int iy = rr / 34, ix = rr - iy * 34;
            const int gy = Y0 - 1 + iy;
            const int gx = X0 - 1 + ix;
            float v = 0.f;
            if (gy >= 0 && gy < NH && gx >= 0 && gx < NW)
                v = xb[((size_t)(cb * TCI + ci) * NH + gy) * NW + gx];
            in_s[ci][iy][ix] = v;
        }
        // stage duplicated weights: TCO*TCI*9 = 144 elements (< 256 threads,
        // single predicated store)
        if (tid < TCO * TCI * 9) {
            const int co = tid / (TCI * 9);
            const int r  = tid - co * (TCI * 9);
            const int ci = r / 9, tap = r - ci * 9;
            const float v =
                wb[((size_t)(cog * TCO + co) * NC + cb * TCI + ci) * 9 + tap];
            w2_s[co][ci][tap] = make_float2(v, v);
        }
        __syncthreads();

        #pragma unroll 1
        for (int ci = 0; ci < TCI; ci++) {
            // full 4-row window: E (even pairs) + O (odd pairs), 20 ull live
            ull E[4][3], O[4][2];
            #pragma unroll
            for (int r = 0; r < 4; r++) {
                const float* row = &in_s[ci][py * 2 + r][px * 4];
                const float4 a = *(const float4*)row;
                const float2 bv = *(const float2*)(row + 4);
                PACK2(E[r][0], a.x, a.y);
                PACK2(E[r][1], a.z, a.w);
                PACK2(E[r][2], bv.x, bv.y);
                PACK2(O[r][0], a.y, a.z);
                PACK2(O[r][1], a.w, bv.x);
            }

            #pragma unroll
            for (int co = 0; co < TCO; co++) {
                const ull* wp = (const ull*)&w2_s[co][ci][0];
                #pragma unroll
                for (int ky = 0; ky < 3; ky++) {
                    const ull w0 = wp[ky * 3 + 0];
                    FMA2(acc2[co][0][0], E[ky    ][0], w0);
                    FMA2(acc2[co][0][1], E[ky    ][1], w0);
                    FMA2(acc2[co][1][0], E[ky + 1][0], w0);
                    FMA2(acc2[co][1][1], E[ky + 1][1], w0);
                    const ull w1 = wp[ky * 3 + 1];
                    FMA2(acc2[co][0][0], O[ky    ][0], w1);
                    FMA2(acc2[co][0][1], O[ky    ][1], w1);
                    FMA2(acc2[co][1][0], O[ky + 1][0], w1);
                    FMA2(acc2[co][1][1], O[ky + 1][1], w1);
                    const ull w2 = wp[ky * 3 + 2];
                    FMA2(acc2[co][0][0], E[ky    ][1], w2);
                    FMA2(acc2[co][0][1], E[ky    ][2], w2);
                    FMA2(acc2[co][1][0], E[ky + 1][1], w2);
                    FMA2(acc2[co][1][1], E[ky + 1][2], w2);
                }
            }
        }
    }

    // epilogue: bias + residual, float4 stores
    const int oy0 = Y0 + py * 2;
    const int ox0 = X0 + px * 4;
    #pragma unroll
    for (int co = 0; co < TCO; co++) {
        const int cg = cog * TCO + co;
        const float bias = g_bcomb[b][cg];
        #pragma unroll
        for (int dy = 0; dy < 2; dy++) {
            const size_t o = ((size_t)(b * NC + cg) * NH + (oy0 + dy)) * NW + ox0;
            float a0, a1, a2, a3;
            UNPACK2(a0, a1, acc2[co][dy][0]);
            UNPACK2(a2, a3, acc2[co][dy][1]);
            const float4 res = *(const float4*)(x + o);
            float4 v;
            v.x = a0 + bias + res.x;
            v.y = a1 + bias + res.y;
            v.z = a2 + bias + res.z;
            v.w = a3 + bias + res.w;
            *(float4*)(out + o) = v;
        }
    }
}

extern "C" void kernel_launch(void* const* d_in, const int* in_sizes, int n_in,
                              void* d_out, int out_size) {
    const float* x     = (const float*)d_in[0];
    const float* wg1   = (const float*)d_in[1];
    const float* bg1   = (const float*)d_in[2];
    const float* wg2   = (const float*)d_in[3];
    const float* bg2   = (const float*)d_in[4];
    const float* w_exp = (const float*)d_in[5];
    const float* b_exp = (const float*)d_in[6];
    float* out = (float*)d_out;

    pool_kernel<<<NB * NC, 256>>>(x);
    gate_kernel<<<NB, 64>>>(wg1, bg1, wg2, bg2);

    const int total = NB * NC * NC * 9;
    combine_kernel<<<(total + 255) / 256, 256>>>(w_exp, b_exp);

    dim3 grid(8, NC / TCO, NB);
    conv_kernel<<<grid, 256>>>(x, out);
}

// round 12
// speedup vs baseline: 4.3322x; 4.3322x over previous
#include <cuda_runtime.h>
#include <cuda_bf16.h>

#define NB 16
#define NC 64
#define NH 128
#define NW 128
#define NE 8
#define NGH 16

__device__ float g_pooled[NB * NC];
__device__ float g_probs[NB][NE];
__device__ float g_bcomb[NB][NC];
// split-bf16 combined weights, layout [b][tap][co][ci]
__device__ __nv_bfloat16 g_wh[NB * 9 * NC * NC];
__device__ __nv_bfloat16 g_wl[NB * 9 * NC * NC];

// ---------------------------------------------------------------------------
// MMA / ldmatrix helpers
// ---------------------------------------------------------------------------
__device__ __forceinline__ unsigned smem_u32(const void* p) {
    return (unsigned)__cvta_generic_to_shared(p);
}

#define LDSM_X4(r0, r1, r2, r3, addr) \
    asm volatile("ldmatrix.sync.aligned.m8n8.x4.shared.b16 {%0,%1,%2,%3}, [%4];" \
                 : "=r"(r0), "=r"(r1), "=r"(r2), "=r"(r3) : "r"(addr))

#define LDSM_X2(r0, r1, addr) \
    asm volatile("ldmatrix.sync.aligned.m8n8.x2.shared.b16 {%0,%1}, [%2];" \
                 : "=r"(r0), "=r"(r1) : "r"(addr))

#define MMA_BF16(d, a0, a1, a2, a3, b0, b1) \
    asm volatile("mma.sync.aligned.m16n8k16.row.col.f32.bf16.bf16.f32 " \
                 "{%0,%1,%2,%3}, {%4,%5,%6,%7}, {%8,%9}, {%0,%1,%2,%3};" \
                 : "+f"(d[0]), "+f"(d[1]), "+f"(d[2]), "+f"(d[3]) \
                 : "r"(a0), "r"(a1), "r"(a2), "r"(a3), "r"(b0), "r"(b1))

// ---------------------------------------------------------------------------
// Kernel 1a: parallel GAP. One block per (b, c).
// ---------------------------------------------------------------------------
__global__ __launch_bounds__(256)
void pool_kernel(const float* __restrict__ x) {
    const int bc = blockIdx.x;
    const int tid = threadIdx.x;
    const float4* p4 = (const float4*)(x + (size_t)bc * NH * NW);

    float s = 0.f;
    #pragma unroll 4
    for (int i = tid; i < (NH * NW) / 4; i += 256) {
        float4 v = p4[i];
        s += (v.x + v.y) + (v.z + v.w);
    }
    #pragma unroll
    for (int o = 16; o > 0; o >>= 1) s += __shfl_xor_sync(0xffffffffu, s, o);

    __shared__ float ws[8];
    if ((tid & 31) == 0) ws[tid >> 5] = s;
    __syncthreads();
    if (tid == 0) {
        float t = 0.f;
        #pragma unroll
        for (int w = 0; w < 8; w++) t += ws[w];
        g_pooled[bc] = t * (1.0f / (NH * NW));
    }
}

// ---------------------------------------------------------------------------
// Kernel 1b: gating MLP + softmax + top-2.
// ---------------------------------------------------------------------------
__global__ void gate_kernel(const float* __restrict__ wg1,
                            const float* __restrict__ bg1,
                            const float* __restrict__ wg2,
                            const float* __restrict__ bg2) {
    const int b = blockIdx.x;
    const int tid = threadIdx.x;  // 64 threads

    __shared__ float pooled[NC];
    __shared__ float hbuf[NGH];
    __shared__ float logits[NE];

    if (tid < NC) pooled[tid] = g_pooled[b * NC + tid];
    __syncthreads();

    if (tid < NGH) {
        float a = bg1[tid];
        #pragma unroll
        for (int c = 0; c < NC; c++) a += pooled[c] * wg1[c * NGH + tid];
        hbuf[tid] = a > 0.f ? a : 0.f;
    }
    __syncthreads();

    if (tid < NE) {
        float a = bg2[tid];
        #pragma unroll
        for (int g = 0; g < NGH; g++) a += hbuf[g] * wg2[g * NE + tid];
        logits[tid] = a;
    }
    __syncthreads();

    if (tid == 0) {
        float m = -1e30f;
        #pragma unroll
        for (int e = 0; e < NE; e++) m = fmaxf(m, logits[e]);
        float p[NE], s = 0.f;
        #pragma unroll
        for (int e = 0; e < NE; e++) { p[e] = expf(logits[e] - m); s += p[e]; }
        float inv = 1.0f / s;
        #pragma unroll
        for (int e = 0; e < NE; e++) p[e] *= inv;
        int i1 = 0;
        #pragma unroll
        for (int e = 1; e < NE; e++) if (p[e] > p[i1]) i1 = e;
        int i2 = -1;
        #pragma unroll
        for (int e = 0; e < NE; e++) {
            if (e == i1) continue;
            if (i2 < 0 || p[e] > p[i2]) i2 = e;
        }
        float denom = p[i1] + p[i2] + 1e-8f;
        #pragma unroll
        for (int e = 0; e < NE; e++)
            g_probs[b][e] = (e == i1 || e == i2) ? p[e] / denom : 0.f;
    }
}

// ---------------------------------------------------------------------------
// Kernel 2: fold routing probs into per-batch weights, split into bf16 hi/lo.
// Output layout [b][tap][co][ci].
// ---------------------------------------------------------------------------
__global__ void combine_kernel(const float* __restrict__ w_exp,
                               const float* __restrict__ b_exp) {
    const int idx = blockIdx.x * blockDim.x + threadIdx.x;
    const int total = NB * 9 * NC * NC;
    if (idx < total) {
        const int b   = idx / (9 * NC * NC);
        const int r   = idx - b * (9 * NC * NC);
        const int tap = r / (NC * NC);
        const int r2  = r - tap * (NC * NC);
        const int co  = r2 / NC;
        const int ci  = r2 - co * NC;
        float s = 0.f;
        #pragma unroll
        for (int e = 0; e < NE; e++)
            s += g_probs[b][e] * w_exp[((size_t)(e * NC + co) * NC + ci) * 9 + tap];
        __nv_bfloat16 hi = __float2bfloat16(s);
        __nv_bfloat16 lo = __float2bfloat16(s - __bfloat162float(hi));
        g_wh[idx] = hi;
        g_wl[idx] = lo;
    }
    if (idx < NB * NC) {
        const int b = idx / NC, c = idx - b * NC;
        float s = 0.f;
        #pragma unroll
        for (int e = 0; e < NE; e++) s += g_probs[b][e] * b_exp[e * NC + c];
        g_bcomb[b][c] = s;
    }
}

// ---------------------------------------------------------------------------
// Kernel 3: implicit-GEMM conv via mma.sync bf16, 3-pass hi/lo split.
// CTA: one 16(h) x 8(w) output tile of one batch. D = [64 co x 128 px].
// smem B: padded 18x10 input tile as [row=pixel][ci] bf16 (hi, lo), 128B rows,
// 16B-unit XOR swizzle. Tap shift = B row offset. 8 warps: mw=warp&3 (co16),
// nw=warp>>2 (px64). Per warp: 8 n8 frags, acc float[8][4].
// ---------------------------------------------------------------------------
#define TPY 16
#define TPX 8
#define PROWS ((TPY + 2) * (TPX + 2))   // 180
#define SMEM_BYTES ((PROWS * NC * 2 + NC * NC * 2) * 2)  // 62464

__global__ __launch_bounds__(256)
void conv_mma_kernel(const float* __restrict__ x, float* __restrict__ out) {
    const int b  = blockIdx.z;
    const int X0 = blockIdx.x * TPX;
    const int Y0 = blockIdx.y * TPY;

    extern __shared__ __align__(16) char smem_raw[];
    __nv_bfloat16* Bh = (__nv_bfloat16*)smem_raw;        // [180][64]
    __nv_bfloat16* Bl = Bh + PROWS * NC;
    __nv_bfloat16* Ah = Bl + PROWS * NC;                 // [64][64]
    __nv_bfloat16* Al = Ah + NC * NC;

    const int tid  = threadIdx.x;
    const int lane = tid & 31;
    const int warp = tid >> 5;
    const int mw = warp & 3;      // co 16-chunk
    const int nw = warp >> 2;     // px 64-chunk

    // ---- stage input tile (hi/lo split, swizzled) ----
    const float* xb = x + (size_t)b * NC * NH * NW;
    for (int i = tid; i < PROWS * NC; i += 256) {
        const int ci = i / PROWS;
        const int r  = i - ci * PROWS;
        const int ly = r / (TPX + 2), lx = r - ly * (TPX + 2);
        const int gy = Y0 - 1 + ly, gx = X0 - 1 + lx;
        float v = 0.f;
        if (gy >= 0 && gy < NH && gx >= 0 && gx < NW)
            v = xb[ci * (NH * NW) + gy * NW + gx];
        const __nv_bfloat16 hi = __float2bfloat16(v);
        const __nv_bfloat16 lo = __float2bfloat16(v - __bfloat162float(hi));
        const int off = r * NC + ((((ci >> 3) ^ (r & 7)) << 3) | (ci & 7));
        Bh[off] = hi;
        Bl[off] = lo;
    }

    const unsigned BhB = smem_u32(Bh), BlB = smem_u32(Bl);
    const unsigned AhB = smem_u32(Ah), AlB = smem_u32(Al);

    // lane-derived ldmatrix address components
    const int l15   = lane & 15;
    const int am    = (mw << 4) + l15;   // A row (co)
    const int khalf = lane >> 4;         // A: k-half select
    const int jx    = l15 & 7;           // B: x within n8 frag
    const int bhalf = l15 >> 3;          // B: k-half select

    float acc[8][4];
    #pragma unroll
    for (int f = 0; f < 8; f++)
        #pragma unroll
        for (int q = 0; q < 4; q++) acc[f][q] = 0.f;

    for (int tap = 0; tap < 9; tap++) {
        __syncthreads();   // prior-tap A reads done (and B staging on tap 0)
        // ---- stage A (weights) for this tap, hi+lo, swizzled ----
        {
            const unsigned* sh = (const unsigned*)g_wh + ((b * 9 + tap) << 11);
            const unsigned* sl = (const unsigned*)g_wl + ((b * 9 + tap) << 11);
            for (int j = tid; j < 2048; j += 256) {
                const int row = j >> 5, q = j & 31;
                const int doff = (row << 5) + ((((q >> 2) ^ (row & 7)) << 2) | (q & 3));
                ((unsigned*)Ah)[doff] = sh[j];
                ((unsigned*)Al)[doff] = sl[j];
            }
        }
        __syncthreads();

        const int ky = tap / 3, kx = tap - ky * 3;
        const int rbase = (nw * 8 + ky) * (TPX + 2) + jx + kx;

        #pragma unroll
        for (int kc = 0; kc < 4; kc++) {
            const unsigned au =
                (unsigned)((am << 7) + ((((kc << 1) | khalf) ^ (am & 7)) << 4));
            unsigned ah0, ah1, ah2, ah3, al0, al1, al2, al3;
            LDSM_X4(ah0, ah1, ah2, ah3, AhB + au);
            LDSM_X4(al0, al1, al2, al3, AlB + au);
            #pragma unroll
            for (int f = 0; f < 8; f++) {
                const int row = rbase + f * (TPX + 2);
                const unsigned bu =
                    (unsigned)((row << 7) + ((((kc << 1) | bhalf) ^ (row & 7)) << 4));
                unsigned bh0, bh1, bl0, bl1;
                LDSM_X2(bh0, bh1, BhB + bu);
                LDSM_X2(bl0, bl1, BlB + bu);
                MMA_BF16(acc[f], ah0, ah1, ah2, ah3, bh0, bh1);
                MMA_BF16(acc[f], ah0, ah1, ah2, ah3, bl0, bl1);
                MMA_BF16(acc[f], al0, al1, al2, al3, bh0, bh1);
            }
        }
    }

    // ---- epilogue: bias + residual ----
    const int r0 = lane >> 2;            // 0..7
    const int c0 = (lane & 3) << 1;      // 0,2,4,6
    #pragma unroll
    for (int f = 0; f < 8; f++) {
        const int n = (nw << 6) + (f << 3) + c0;
        const int y = Y0 + (n >> 3);
        const int xg = X0 + (n & 7);
        #pragma unroll
        for (int h = 0; h < 2; h++) {
            const int co = mw * 16 + r0 + h * 8;
            const float bias = g_bcomb[b][co];
            const size_t o = ((size_t)(b * NC + co) * NH + y) * NW + xg;
            const float2 res = *(const float2*)(x + o);
            float2 v;
            v.x = acc[f][h * 2 + 0] + bias + res.x;
            v.y = acc[f][h * 2 + 1] + bias + res.y;
            *(float2*)(out + o) = v;
        }
    }
}

extern "C" void kernel_launch(void* const* d_in, const int* in_sizes, int n_in,
                              void* d_out, int out_size) {
    const float* x     = (const float*)d_in[0];
    const float* wg1   = (const float*)d_in[1];
    const float* bg1   = (const float*)d_in[2];
    const float* wg2   = (const float*)d_in[3];
    const float* bg2   = (const float*)d_in[4];
    const float* w_exp = (const float*)d_in[5];
    const float* b_exp = (const float*)d_in[6];
    float* out = (float*)d_out;

    pool_kernel<<<NB * NC, 256>>>(x);
    gate_kernel<<<NB, 64>>>(wg1, bg1, wg2, bg2);

    const int total = NB * 9 * NC * NC;
    combine_kernel<<<(total + 255) / 256, 256>>>(w_exp, b_exp);

    static bool attr_set = false;
    if (!attr_set) {
        cudaFuncSetAttribute(conv_mma_kernel,
                             cudaFuncAttributeMaxDynamicSharedMemorySize,
                             SMEM_BYTES);
        attr_set = true;
    }
    dim3 grid(NW / TPX, NH / TPY, NB);   // (16, 8, 16)
    conv_mma_kernel<<<grid, 256, SMEM_BYTES>>>(x, out);
}